// round 3
// baseline (speedup 1.0000x reference)
#include <cuda_runtime.h>
#include <cstdint>
#include <cstddef>

// Problem constants (fixed by setup_inputs)
#define BATCH 4
#define SEQ   1024
#define DIM   1152
#define HEADS 16
#define HDIM  72
#define ROWS  (BATCH*SEQ)          // 4096
#define QKVN  (3*DIM)              // 3456
#define TOTAL_ELEMS 4718592.0f     // B*H*N*hd for loss mean

// Scratch (static device allocation — allowed)
__device__ __align__(16) float g_qkv [(size_t)ROWS * QKVN];   // 56.6 MB, (B*N, 3456)
__device__ __align__(16) float g_xout[(size_t)ROWS * DIM];    // 18.9 MB, (B*N, 1152) = (B,N,H,hd)

// ---------------------------------------------------------------------------
// GEMM: C[m,n] = sum_k A[m,k] * W[n,k] + bias[n]
// BM=128, BN=64, BK=16, 256 threads, 8x4 micro-tile
// ---------------------------------------------------------------------------
__global__ __launch_bounds__(256)
void gemm_bias_kernel(const float* __restrict__ A, const float* __restrict__ W,
                      const float* __restrict__ bias, float* __restrict__ C,
                      int M, int N, int K)
{
    __shared__ __align__(16) float As[16][128];
    __shared__ __align__(16) float Bs[16][64];

    const int tid = threadIdx.x;
    const int tx = tid & 15;         // 0..15 -> n
    const int ty = tid >> 4;         // 0..15 -> m
    const int m0 = blockIdx.y * 128;
    const int n0 = blockIdx.x * 64;

    float acc[8][4];
#pragma unroll
    for (int i = 0; i < 8; i++)
#pragma unroll
        for (int j = 0; j < 4; j++) acc[i][j] = 0.f;

    const int ktiles = K >> 4;
    for (int kt = 0; kt < ktiles; kt++) {
        const int k0 = kt << 4;
        // Load A tile: 128 rows x 16 cols = 512 float4
#pragma unroll
        for (int r = 0; r < 2; r++) {
            int e = tid + r * 256;
            int row = e >> 2;
            int kc  = (e & 3) << 2;
            float4 va = *(const float4*)&A[(size_t)(m0 + row) * K + k0 + kc];
            As[kc + 0][row] = va.x; As[kc + 1][row] = va.y;
            As[kc + 2][row] = va.z; As[kc + 3][row] = va.w;
        }
        // Load B tile: 64 rows x 16 cols = 256 float4
        {
            int row = tid >> 2;
            int kc  = (tid & 3) << 2;
            float4 vb = *(const float4*)&W[(size_t)(n0 + row) * K + k0 + kc];
            Bs[kc + 0][row] = vb.x; Bs[kc + 1][row] = vb.y;
            Bs[kc + 2][row] = vb.z; Bs[kc + 3][row] = vb.w;
        }
        __syncthreads();
#pragma unroll
        for (int k = 0; k < 16; k++) {
            float4 a0 = *(const float4*)&As[k][ty * 8];
            float4 a1 = *(const float4*)&As[k][ty * 8 + 4];
            float4 b  = *(const float4*)&Bs[k][tx * 4];
            float am[8] = {a0.x, a0.y, a0.z, a0.w, a1.x, a1.y, a1.z, a1.w};
            float bn[4] = {b.x, b.y, b.z, b.w};
#pragma unroll
            for (int i = 0; i < 8; i++)
#pragma unroll
                for (int j = 0; j < 4; j++) acc[i][j] += am[i] * bn[j];
        }
        __syncthreads();
    }

    const float4 bv = *(const float4*)&bias[n0 + tx * 4];
#pragma unroll
    for (int i = 0; i < 8; i++) {
        float4 o;
        o.x = acc[i][0] + bv.x; o.y = acc[i][1] + bv.y;
        o.z = acc[i][2] + bv.z; o.w = acc[i][3] + bv.w;
        *(float4*)&C[(size_t)(m0 + ty * 8 + i) * N + n0 + tx * 4] = o;
    }
}

// ---------------------------------------------------------------------------
// Fused dual attention + distill loss.
// grid: (16 q-tiles, 64 bh). block: 256 threads = 8 warps.
// Each warp owns 8 queries; 4 lanes per query, each lane owns 18 dims.
// Pass 0: own K/V (from g_qkv) -> writes g_xout. Pass 1: encoder K/V -> loss.
// ---------------------------------------------------------------------------
__global__ __launch_bounds__(256)
void attn_kernel(const float* __restrict__ enc_k, const float* __restrict__ enc_v,
                 float* __restrict__ loss_out)
{
    __shared__ __align__(16) float Ks[64][72];
    __shared__ __align__(16) float Vs[64][72];

    const int tid  = threadIdx.x;
    const int lane = tid & 31;
    const int warp = tid >> 5;
    const int sub  = lane & 3;                 // 4 lanes per query
    const int qloc = warp * 8 + (lane >> 2);   // 0..63
    const int bh = blockIdx.y;
    const int b  = bh >> 4;
    const int h  = bh & 15;
    const int n  = blockIdx.x * 64 + qloc;
    const float scale = rsqrtf((float)HDIM);

    // Load this lane's 18 Q dims (pre-scaled)
    float2 qr[9];
    {
        const float* qs = g_qkv + ((size_t)(b * SEQ + n)) * QKVN + h * HDIM + sub * 18;
#pragma unroll
        for (int j = 0; j < 9; j++) {
            float2 v = ((const float2*)qs)[j];
            qr[j].x = v.x * scale; qr[j].y = v.y * scale;
        }
    }

    float xo[18];           // pass-0 output, kept for loss
    float lsum = 0.f;

    for (int p = 0; p < 2; p++) {
        float m = -1e30f, l = 0.f;
        float2 O[9];
#pragma unroll
        for (int j = 0; j < 9; j++) O[j] = make_float2(0.f, 0.f);

        for (int kt = 0; kt < 16; kt++) {
            float2* ksm = (float2*)&Ks[0][0];
            float2* vsm = (float2*)&Vs[0][0];
            if (p == 0) {
#pragma unroll
                for (int r = 0; r < 9; r++) {
                    int e = tid + r * 256;            // 0..2303 (float2 units)
                    int key = e / 36;
                    int dp  = e - key * 36;
                    size_t base = ((size_t)(b * SEQ + kt * 64 + key)) * QKVN + h * HDIM + dp * 2;
                    ksm[e] = *(const float2*)(g_qkv + base + DIM);
                    vsm[e] = *(const float2*)(g_qkv + base + 2 * DIM);
                }
            } else {
                const float2* kst = (const float2*)(enc_k + ((size_t)bh * SEQ + kt * 64) * HDIM);
                const float2* vst = (const float2*)(enc_v + ((size_t)bh * SEQ + kt * 64) * HDIM);
#pragma unroll
                for (int r = 0; r < 9; r++) {
                    int e = tid + r * 256;
                    ksm[e] = kst[e];
                    vsm[e] = vst[e];
                }
            }
            __syncthreads();

            // Scores for 64 keys; each lane keeps 16 of them (static indices)
            float sc[16];
            float tmax = -1e30f;
#pragma unroll
            for (int i = 0; i < 16; i++) {
#pragma unroll
                for (int u = 0; u < 4; u++) {
                    const int kk = i * 4 + u;
                    const float2* kr = (const float2*)&Ks[kk][sub * 18];
                    float s = 0.f;
#pragma unroll
                    for (int j = 0; j < 9; j++) {
                        float2 kv = kr[j];
                        s += qr[j].x * kv.x + qr[j].y * kv.y;
                    }
                    s += __shfl_xor_sync(0xffffffffu, s, 1);
                    s += __shfl_xor_sync(0xffffffffu, s, 2);   // full dot on all 4 lanes
                    if (u == sub) sc[i] = s;
                    tmax = fmaxf(tmax, s);
                }
            }
            // Online softmax update
            float nm = fmaxf(m, tmax);
            float corr = __expf(m - nm);
            l *= corr;
#pragma unroll
            for (int j = 0; j < 9; j++) { O[j].x *= corr; O[j].y *= corr; }
            float ps = 0.f;
#pragma unroll
            for (int i = 0; i < 16; i++) { sc[i] = __expf(sc[i] - nm); ps += sc[i]; }
            ps += __shfl_xor_sync(0xffffffffu, ps, 1);
            ps += __shfl_xor_sync(0xffffffffu, ps, 2);
            l += ps; m = nm;

            // O += P @ V
#pragma unroll
            for (int i = 0; i < 16; i++) {
#pragma unroll
                for (int u = 0; u < 4; u++) {
                    const int kk = i * 4 + u;
                    float pv = __shfl_sync(0xffffffffu, sc[i], (lane & ~3) | u);
                    const float2* vr = (const float2*)&Vs[kk][sub * 18];
#pragma unroll
                    for (int j = 0; j < 9; j++) {
                        float2 vv = vr[j];
                        O[j].x += pv * vv.x; O[j].y += pv * vv.y;
                    }
                }
            }
            __syncthreads();
        }

        const float inv_l = 1.0f / l;
        if (p == 0) {
            float* dst = g_xout + ((size_t)(b * SEQ + n)) * DIM + h * HDIM + sub * 18;
#pragma unroll
            for (int j = 0; j < 9; j++) {
                xo[2 * j]     = O[j].x * inv_l;
                xo[2 * j + 1] = O[j].y * inv_l;
                ((float2*)dst)[j] = make_float2(xo[2 * j], xo[2 * j + 1]);
            }
        } else {
#pragma unroll
            for (int j = 0; j < 9; j++) {
                float d0 = xo[2 * j]     - O[j].x * inv_l;
                float d1 = xo[2 * j + 1] - O[j].y * inv_l;
                lsum += d0 * d0 + d1 * d1;
            }
        }
    }

    // Loss: mean over all elements; warp-reduce then one atomic per warp
    lsum *= (1.0f / TOTAL_ELEMS);
#pragma unroll
    for (int o = 16; o > 0; o >>= 1)
        lsum += __shfl_down_sync(0xffffffffu, lsum, o);
    if (lane == 0) atomicAdd(loss_out, lsum);
}

// ---------------------------------------------------------------------------
extern "C" void kernel_launch(void* const* d_in, const int* in_sizes, int n_in,
                              void* d_out, int out_size)
{
    const float* x      = (const float*)d_in[0];
    const float* enc_k  = (const float*)d_in[1];
    const float* enc_v  = (const float*)d_in[2];
    const float* qkv_w  = (const float*)d_in[3];
    const float* qkv_b  = (const float*)d_in[4];
    const float* proj_w = (const float*)d_in[5];
    const float* proj_b = (const float*)d_in[6];
    float* out = (float*)d_out;
    float* loss_ptr = out + (out_size - 1);

    float* qkv_ptr = nullptr;
    float* xout_ptr = nullptr;
    cudaGetSymbolAddress((void**)&qkv_ptr,  g_qkv);
    cudaGetSymbolAddress((void**)&xout_ptr, g_xout);

    cudaMemsetAsync(loss_ptr, 0, sizeof(float));

    // 1) QKV GEMM: (4096,1152) @ (3456,1152)^T + b -> g_qkv (4096,3456)
    gemm_bias_kernel<<<dim3(QKVN / 64, ROWS / 128), 256>>>(
        x, qkv_w, qkv_b, qkv_ptr, ROWS, QKVN, DIM);

    // 2) Dual attention + loss -> g_xout (4096,1152), loss scalar
    attn_kernel<<<dim3(SEQ / 64, BATCH * HEADS), 256>>>(enc_k, enc_v, loss_ptr);

    // 3) Proj GEMM: (4096,1152) @ (1152,1152)^T + b -> out
    gemm_bias_kernel<<<dim3(DIM / 64, ROWS / 128), 256>>>(
        xout_ptr, proj_w, proj_b, out, ROWS, DIM, DIM);
}

// round 4
// speedup vs baseline: 1.0002x; 1.0002x over previous
#include <cuda_runtime.h>
#include <cstdint>
#include <cstddef>

// Problem constants (fixed by setup_inputs)
#define BATCH 4
#define SEQ   1024
#define DIM   1152
#define HEADS 16
#define HDIM  72
#define ROWS  (BATCH*SEQ)          // 4096
#define QKVN  (3*DIM)              // 3456
#define TOTAL_ELEMS 4718592.0f     // B*H*N*hd for loss mean

// Scratch (static device allocation — allowed)
__device__ __align__(16) float g_qkv [(size_t)ROWS * QKVN];   // 56.6 MB, (B*N, 3456)
__device__ __align__(16) float g_xout[(size_t)ROWS * DIM];    // 18.9 MB, (B*N, 1152) = (B,N,H,hd)

// ---------------------------------------------------------------------------
// GEMM: C[m,n] = sum_k A[m,k] * W[n,k] + bias[n]
// BM=128, BN=64, BK=16, 256 threads, 8x4 micro-tile
// ---------------------------------------------------------------------------
__global__ __launch_bounds__(256)
void gemm_bias_kernel(const float* __restrict__ A, const float* __restrict__ W,
                      const float* __restrict__ bias, float* __restrict__ C,
                      int M, int N, int K)
{
    __shared__ __align__(16) float As[16][128];
    __shared__ __align__(16) float Bs[16][64];

    const int tid = threadIdx.x;
    const int tx = tid & 15;         // 0..15 -> n
    const int ty = tid >> 4;         // 0..15 -> m
    const int m0 = blockIdx.y * 128;
    const int n0 = blockIdx.x * 64;

    float acc[8][4];
#pragma unroll
    for (int i = 0; i < 8; i++)
#pragma unroll
        for (int j = 0; j < 4; j++) acc[i][j] = 0.f;

    const int ktiles = K >> 4;
    for (int kt = 0; kt < ktiles; kt++) {
        const int k0 = kt << 4;
        // Load A tile: 128 rows x 16 cols = 512 float4
#pragma unroll
        for (int r = 0; r < 2; r++) {
            int e = tid + r * 256;
            int row = e >> 2;
            int kc  = (e & 3) << 2;
            float4 va = *(const float4*)&A[(size_t)(m0 + row) * K + k0 + kc];
            As[kc + 0][row] = va.x; As[kc + 1][row] = va.y;
            As[kc + 2][row] = va.z; As[kc + 3][row] = va.w;
        }
        // Load B tile: 64 rows x 16 cols = 256 float4
        {
            int row = tid >> 2;
            int kc  = (tid & 3) << 2;
            float4 vb = *(const float4*)&W[(size_t)(n0 + row) * K + k0 + kc];
            Bs[kc + 0][row] = vb.x; Bs[kc + 1][row] = vb.y;
            Bs[kc + 2][row] = vb.z; Bs[kc + 3][row] = vb.w;
        }
        __syncthreads();
#pragma unroll
        for (int k = 0; k < 16; k++) {
            float4 a0 = *(const float4*)&As[k][ty * 8];
            float4 a1 = *(const float4*)&As[k][ty * 8 + 4];
            float4 b  = *(const float4*)&Bs[k][tx * 4];
            float am[8] = {a0.x, a0.y, a0.z, a0.w, a1.x, a1.y, a1.z, a1.w};
            float bn[4] = {b.x, b.y, b.z, b.w};
#pragma unroll
            for (int i = 0; i < 8; i++)
#pragma unroll
                for (int j = 0; j < 4; j++) acc[i][j] += am[i] * bn[j];
        }
        __syncthreads();
    }

    const float4 bv = *(const float4*)&bias[n0 + tx * 4];
#pragma unroll
    for (int i = 0; i < 8; i++) {
        float4 o;
        o.x = acc[i][0] + bv.x; o.y = acc[i][1] + bv.y;
        o.z = acc[i][2] + bv.z; o.w = acc[i][3] + bv.w;
        *(float4*)&C[(size_t)(m0 + ty * 8 + i) * N + n0 + tx * 4] = o;
    }
}

// ---------------------------------------------------------------------------
// Fused dual attention + distill loss.
// grid: (16 q-tiles, 64 bh). block: 256 threads = 8 warps.
// Each warp owns 8 queries; 4 lanes per query, each lane owns 18 dims.
// Pass 0: own K/V (from g_qkv) -> writes g_xout. Pass 1: encoder K/V -> loss.
// ---------------------------------------------------------------------------
__global__ __launch_bounds__(256)
void attn_kernel(const float* __restrict__ enc_k, const float* __restrict__ enc_v,
                 float* __restrict__ loss_out)
{
    __shared__ __align__(16) float Ks[64][72];
    __shared__ __align__(16) float Vs[64][72];

    const int tid  = threadIdx.x;
    const int lane = tid & 31;
    const int warp = tid >> 5;
    const int sub  = lane & 3;                 // 4 lanes per query
    const int qloc = warp * 8 + (lane >> 2);   // 0..63
    const int bh = blockIdx.y;
    const int b  = bh >> 4;
    const int h  = bh & 15;
    const int n  = blockIdx.x * 64 + qloc;
    const float scale = rsqrtf((float)HDIM);

    // Load this lane's 18 Q dims (pre-scaled)
    float2 qr[9];
    {
        const float* qs = g_qkv + ((size_t)(b * SEQ + n)) * QKVN + h * HDIM + sub * 18;
#pragma unroll
        for (int j = 0; j < 9; j++) {
            float2 v = ((const float2*)qs)[j];
            qr[j].x = v.x * scale; qr[j].y = v.y * scale;
        }
    }

    float xo[18];           // pass-0 output, kept for loss
    float lsum = 0.f;

    for (int p = 0; p < 2; p++) {
        float m = -1e30f, l = 0.f;
        float2 O[9];
#pragma unroll
        for (int j = 0; j < 9; j++) O[j] = make_float2(0.f, 0.f);

        for (int kt = 0; kt < 16; kt++) {
            float2* ksm = (float2*)&Ks[0][0];
            float2* vsm = (float2*)&Vs[0][0];
            if (p == 0) {
#pragma unroll
                for (int r = 0; r < 9; r++) {
                    int e = tid + r * 256;            // 0..2303 (float2 units)
                    int key = e / 36;
                    int dp  = e - key * 36;
                    size_t base = ((size_t)(b * SEQ + kt * 64 + key)) * QKVN + h * HDIM + dp * 2;
                    ksm[e] = *(const float2*)(g_qkv + base + DIM);
                    vsm[e] = *(const float2*)(g_qkv + base + 2 * DIM);
                }
            } else {
                const float2* kst = (const float2*)(enc_k + ((size_t)bh * SEQ + kt * 64) * HDIM);
                const float2* vst = (const float2*)(enc_v + ((size_t)bh * SEQ + kt * 64) * HDIM);
#pragma unroll
                for (int r = 0; r < 9; r++) {
                    int e = tid + r * 256;
                    ksm[e] = kst[e];
                    vsm[e] = vst[e];
                }
            }
            __syncthreads();

            // Scores for 64 keys; each lane keeps 16 of them (static indices)
            float sc[16];
            float tmax = -1e30f;
#pragma unroll
            for (int i = 0; i < 16; i++) {
#pragma unroll
                for (int u = 0; u < 4; u++) {
                    const int kk = i * 4 + u;
                    const float2* kr = (const float2*)&Ks[kk][sub * 18];
                    float s = 0.f;
#pragma unroll
                    for (int j = 0; j < 9; j++) {
                        float2 kv = kr[j];
                        s += qr[j].x * kv.x + qr[j].y * kv.y;
                    }
                    s += __shfl_xor_sync(0xffffffffu, s, 1);
                    s += __shfl_xor_sync(0xffffffffu, s, 2);   // full dot on all 4 lanes
                    if (u == sub) sc[i] = s;
                    tmax = fmaxf(tmax, s);
                }
            }
            // Online softmax update
            float nm = fmaxf(m, tmax);
            float corr = __expf(m - nm);
            l *= corr;
#pragma unroll
            for (int j = 0; j < 9; j++) { O[j].x *= corr; O[j].y *= corr; }
            float ps = 0.f;
#pragma unroll
            for (int i = 0; i < 16; i++) { sc[i] = __expf(sc[i] - nm); ps += sc[i]; }
            ps += __shfl_xor_sync(0xffffffffu, ps, 1);
            ps += __shfl_xor_sync(0xffffffffu, ps, 2);
            l += ps; m = nm;

            // O += P @ V
#pragma unroll
            for (int i = 0; i < 16; i++) {
#pragma unroll
                for (int u = 0; u < 4; u++) {
                    const int kk = i * 4 + u;
                    float pv = __shfl_sync(0xffffffffu, sc[i], (lane & ~3) | u);
                    const float2* vr = (const float2*)&Vs[kk][sub * 18];
#pragma unroll
                    for (int j = 0; j < 9; j++) {
                        float2 vv = vr[j];
                        O[j].x += pv * vv.x; O[j].y += pv * vv.y;
                    }
                }
            }
            __syncthreads();
        }

        const float inv_l = 1.0f / l;
        if (p == 0) {
            float* dst = g_xout + ((size_t)(b * SEQ + n)) * DIM + h * HDIM + sub * 18;
#pragma unroll
            for (int j = 0; j < 9; j++) {
                xo[2 * j]     = O[j].x * inv_l;
                xo[2 * j + 1] = O[j].y * inv_l;
                ((float2*)dst)[j] = make_float2(xo[2 * j], xo[2 * j + 1]);
            }
        } else {
#pragma unroll
            for (int j = 0; j < 9; j++) {
                float d0 = xo[2 * j]     - O[j].x * inv_l;
                float d1 = xo[2 * j + 1] - O[j].y * inv_l;
                lsum += d0 * d0 + d1 * d1;
            }
        }
    }

    // Loss: mean over all elements; warp-reduce then one atomic per warp
    lsum *= (1.0f / TOTAL_ELEMS);
#pragma unroll
    for (int o = 16; o > 0; o >>= 1)
        lsum += __shfl_down_sync(0xffffffffu, lsum, o);
    if (lane == 0) atomicAdd(loss_out, lsum);
}

// ---------------------------------------------------------------------------
extern "C" void kernel_launch(void* const* d_in, const int* in_sizes, int n_in,
                              void* d_out, int out_size)
{
    const float* x      = (const float*)d_in[0];
    const float* enc_k  = (const float*)d_in[1];
    const float* enc_v  = (const float*)d_in[2];
    const float* qkv_w  = (const float*)d_in[3];
    const float* qkv_b  = (const float*)d_in[4];
    const float* proj_w = (const float*)d_in[5];
    const float* proj_b = (const float*)d_in[6];
    float* out = (float*)d_out;
    float* loss_ptr = out + (out_size - 1);

    float* qkv_ptr = nullptr;
    float* xout_ptr = nullptr;
    cudaGetSymbolAddress((void**)&qkv_ptr,  g_qkv);
    cudaGetSymbolAddress((void**)&xout_ptr, g_xout);

    cudaMemsetAsync(loss_ptr, 0, sizeof(float));

    // 1) QKV GEMM: (4096,1152) @ (3456,1152)^T + b -> g_qkv (4096,3456)
    gemm_bias_kernel<<<dim3(QKVN / 64, ROWS / 128), 256>>>(
        x, qkv_w, qkv_b, qkv_ptr, ROWS, QKVN, DIM);

    // 2) Dual attention + loss -> g_xout (4096,1152), loss scalar
    attn_kernel<<<dim3(SEQ / 64, BATCH * HEADS), 256>>>(enc_k, enc_v, loss_ptr);

    // 3) Proj GEMM: (4096,1152) @ (1152,1152)^T + b -> out
    gemm_bias_kernel<<<dim3(DIM / 64, ROWS / 128), 256>>>(
        xout_ptr, proj_w, proj_b, out, ROWS, DIM, DIM);
}

// round 5
// speedup vs baseline: 1.0004x; 1.0003x over previous
#include <cuda_runtime.h>
#include <cstdint>
#include <cstddef>

// Problem constants (fixed by setup_inputs)
#define BATCH 4
#define SEQ   1024
#define DIM   1152
#define HEADS 16
#define HDIM  72
#define ROWS  (BATCH*SEQ)          // 4096
#define QKVN  (3*DIM)              // 3456
#define TOTAL_ELEMS 4718592.0f     // B*H*N*hd for loss mean

// Scratch (static device allocation — allowed)
__device__ __align__(16) float g_qkv [(size_t)ROWS * QKVN];   // 56.6 MB, (B*N, 3456)
__device__ __align__(16) float g_xout[(size_t)ROWS * DIM];    // 18.9 MB, (B*N, 1152) = (B,N,H,hd)

// ---------------------------------------------------------------------------
// GEMM: C[m,n] = sum_k A[m,k] * W[n,k] + bias[n]
// BM=128, BN=64, BK=16, 256 threads, 8x4 micro-tile
// ---------------------------------------------------------------------------
__global__ __launch_bounds__(256)
void gemm_bias_kernel(const float* __restrict__ A, const float* __restrict__ W,
                      const float* __restrict__ bias, float* __restrict__ C,
                      int M, int N, int K)
{
    __shared__ __align__(16) float As[16][128];
    __shared__ __align__(16) float Bs[16][64];

    const int tid = threadIdx.x;
    const int tx = tid & 15;         // 0..15 -> n
    const int ty = tid >> 4;         // 0..15 -> m
    const int m0 = blockIdx.y * 128;
    const int n0 = blockIdx.x * 64;

    float acc[8][4];
#pragma unroll
    for (int i = 0; i < 8; i++)
#pragma unroll
        for (int j = 0; j < 4; j++) acc[i][j] = 0.f;

    const int ktiles = K >> 4;
    for (int kt = 0; kt < ktiles; kt++) {
        const int k0 = kt << 4;
        // Load A tile: 128 rows x 16 cols = 512 float4
#pragma unroll
        for (int r = 0; r < 2; r++) {
            int e = tid + r * 256;
            int row = e >> 2;
            int kc  = (e & 3) << 2;
            float4 va = *(const float4*)&A[(size_t)(m0 + row) * K + k0 + kc];
            As[kc + 0][row] = va.x; As[kc + 1][row] = va.y;
            As[kc + 2][row] = va.z; As[kc + 3][row] = va.w;
        }
        // Load B tile: 64 rows x 16 cols = 256 float4
        {
            int row = tid >> 2;
            int kc  = (tid & 3) << 2;
            float4 vb = *(const float4*)&W[(size_t)(n0 + row) * K + k0 + kc];
            Bs[kc + 0][row] = vb.x; Bs[kc + 1][row] = vb.y;
            Bs[kc + 2][row] = vb.z; Bs[kc + 3][row] = vb.w;
        }
        __syncthreads();
#pragma unroll
        for (int k = 0; k < 16; k++) {
            float4 a0 = *(const float4*)&As[k][ty * 8];
            float4 a1 = *(const float4*)&As[k][ty * 8 + 4];
            float4 b  = *(const float4*)&Bs[k][tx * 4];
            float am[8] = {a0.x, a0.y, a0.z, a0.w, a1.x, a1.y, a1.z, a1.w};
            float bn[4] = {b.x, b.y, b.z, b.w};
#pragma unroll
            for (int i = 0; i < 8; i++)
#pragma unroll
                for (int j = 0; j < 4; j++) acc[i][j] += am[i] * bn[j];
        }
        __syncthreads();
    }

    const float4 bv = *(const float4*)&bias[n0 + tx * 4];
#pragma unroll
    for (int i = 0; i < 8; i++) {
        float4 o;
        o.x = acc[i][0] + bv.x; o.y = acc[i][1] + bv.y;
        o.z = acc[i][2] + bv.z; o.w = acc[i][3] + bv.w;
        *(float4*)&C[(size_t)(m0 + ty * 8 + i) * N + n0 + tx * 4] = o;
    }
}

// ---------------------------------------------------------------------------
// Fused dual attention + distill loss.
// grid: (16 q-tiles, 64 bh). block: 256 threads = 8 warps.
// Each warp owns 8 queries; 4 lanes per query, each lane owns 18 dims.
// Pass 0: own K/V (from g_qkv) -> writes g_xout. Pass 1: encoder K/V -> loss.
// ---------------------------------------------------------------------------
__global__ __launch_bounds__(256)
void attn_kernel(const float* __restrict__ enc_k, const float* __restrict__ enc_v,
                 float* __restrict__ loss_out)
{
    __shared__ __align__(16) float Ks[64][72];
    __shared__ __align__(16) float Vs[64][72];

    const int tid  = threadIdx.x;
    const int lane = tid & 31;
    const int warp = tid >> 5;
    const int sub  = lane & 3;                 // 4 lanes per query
    const int qloc = warp * 8 + (lane >> 2);   // 0..63
    const int bh = blockIdx.y;
    const int b  = bh >> 4;
    const int h  = bh & 15;
    const int n  = blockIdx.x * 64 + qloc;
    const float scale = rsqrtf((float)HDIM);

    // Load this lane's 18 Q dims (pre-scaled)
    float2 qr[9];
    {
        const float* qs = g_qkv + ((size_t)(b * SEQ + n)) * QKVN + h * HDIM + sub * 18;
#pragma unroll
        for (int j = 0; j < 9; j++) {
            float2 v = ((const float2*)qs)[j];
            qr[j].x = v.x * scale; qr[j].y = v.y * scale;
        }
    }

    float xo[18];           // pass-0 output, kept for loss
    float lsum = 0.f;

    for (int p = 0; p < 2; p++) {
        float m = -1e30f, l = 0.f;
        float2 O[9];
#pragma unroll
        for (int j = 0; j < 9; j++) O[j] = make_float2(0.f, 0.f);

        for (int kt = 0; kt < 16; kt++) {
            float2* ksm = (float2*)&Ks[0][0];
            float2* vsm = (float2*)&Vs[0][0];
            if (p == 0) {
#pragma unroll
                for (int r = 0; r < 9; r++) {
                    int e = tid + r * 256;            // 0..2303 (float2 units)
                    int key = e / 36;
                    int dp  = e - key * 36;
                    size_t base = ((size_t)(b * SEQ + kt * 64 + key)) * QKVN + h * HDIM + dp * 2;
                    ksm[e] = *(const float2*)(g_qkv + base + DIM);
                    vsm[e] = *(const float2*)(g_qkv + base + 2 * DIM);
                }
            } else {
                const float2* kst = (const float2*)(enc_k + ((size_t)bh * SEQ + kt * 64) * HDIM);
                const float2* vst = (const float2*)(enc_v + ((size_t)bh * SEQ + kt * 64) * HDIM);
#pragma unroll
                for (int r = 0; r < 9; r++) {
                    int e = tid + r * 256;
                    ksm[e] = kst[e];
                    vsm[e] = vst[e];
                }
            }
            __syncthreads();

            // Scores for 64 keys; each lane keeps 16 of them (static indices)
            float sc[16];
            float tmax = -1e30f;
#pragma unroll
            for (int i = 0; i < 16; i++) {
#pragma unroll
                for (int u = 0; u < 4; u++) {
                    const int kk = i * 4 + u;
                    const float2* kr = (const float2*)&Ks[kk][sub * 18];
                    float s = 0.f;
#pragma unroll
                    for (int j = 0; j < 9; j++) {
                        float2 kv = kr[j];
                        s += qr[j].x * kv.x + qr[j].y * kv.y;
                    }
                    s += __shfl_xor_sync(0xffffffffu, s, 1);
                    s += __shfl_xor_sync(0xffffffffu, s, 2);   // full dot on all 4 lanes
                    if (u == sub) sc[i] = s;
                    tmax = fmaxf(tmax, s);
                }
            }
            // Online softmax update
            float nm = fmaxf(m, tmax);
            float corr = __expf(m - nm);
            l *= corr;
#pragma unroll
            for (int j = 0; j < 9; j++) { O[j].x *= corr; O[j].y *= corr; }
            float ps = 0.f;
#pragma unroll
            for (int i = 0; i < 16; i++) { sc[i] = __expf(sc[i] - nm); ps += sc[i]; }
            ps += __shfl_xor_sync(0xffffffffu, ps, 1);
            ps += __shfl_xor_sync(0xffffffffu, ps, 2);
            l += ps; m = nm;

            // O += P @ V
#pragma unroll
            for (int i = 0; i < 16; i++) {
#pragma unroll
                for (int u = 0; u < 4; u++) {
                    const int kk = i * 4 + u;
                    float pv = __shfl_sync(0xffffffffu, sc[i], (lane & ~3) | u);
                    const float2* vr = (const float2*)&Vs[kk][sub * 18];
#pragma unroll
                    for (int j = 0; j < 9; j++) {
                        float2 vv = vr[j];
                        O[j].x += pv * vv.x; O[j].y += pv * vv.y;
                    }
                }
            }
            __syncthreads();
        }

        const float inv_l = 1.0f / l;
        if (p == 0) {
            float* dst = g_xout + ((size_t)(b * SEQ + n)) * DIM + h * HDIM + sub * 18;
#pragma unroll
            for (int j = 0; j < 9; j++) {
                xo[2 * j]     = O[j].x * inv_l;
                xo[2 * j + 1] = O[j].y * inv_l;
                ((float2*)dst)[j] = make_float2(xo[2 * j], xo[2 * j + 1]);
            }
        } else {
#pragma unroll
            for (int j = 0; j < 9; j++) {
                float d0 = xo[2 * j]     - O[j].x * inv_l;
                float d1 = xo[2 * j + 1] - O[j].y * inv_l;
                lsum += d0 * d0 + d1 * d1;
            }
        }
    }

    // Loss: mean over all elements; warp-reduce then one atomic per warp
    lsum *= (1.0f / TOTAL_ELEMS);
#pragma unroll
    for (int o = 16; o > 0; o >>= 1)
        lsum += __shfl_down_sync(0xffffffffu, lsum, o);
    if (lane == 0) atomicAdd(loss_out, lsum);
}

// ---------------------------------------------------------------------------
extern "C" void kernel_launch(void* const* d_in, const int* in_sizes, int n_in,
                              void* d_out, int out_size)
{
    const float* x      = (const float*)d_in[0];
    const float* enc_k  = (const float*)d_in[1];
    const float* enc_v  = (const float*)d_in[2];
    const float* qkv_w  = (const float*)d_in[3];
    const float* qkv_b  = (const float*)d_in[4];
    const float* proj_w = (const float*)d_in[5];
    const float* proj_b = (const float*)d_in[6];
    float* out = (float*)d_out;
    float* loss_ptr = out + (out_size - 1);

    float* qkv_ptr = nullptr;
    float* xout_ptr = nullptr;
    cudaGetSymbolAddress((void**)&qkv_ptr,  g_qkv);
    cudaGetSymbolAddress((void**)&xout_ptr, g_xout);

    cudaMemsetAsync(loss_ptr, 0, sizeof(float));

    // 1) QKV GEMM: (4096,1152) @ (3456,1152)^T + b -> g_qkv (4096,3456)
    gemm_bias_kernel<<<dim3(QKVN / 64, ROWS / 128), 256>>>(
        x, qkv_w, qkv_b, qkv_ptr, ROWS, QKVN, DIM);

    // 2) Dual attention + loss -> g_xout (4096,1152), loss scalar
    attn_kernel<<<dim3(SEQ / 64, BATCH * HEADS), 256>>>(enc_k, enc_v, loss_ptr);

    // 3) Proj GEMM: (4096,1152) @ (1152,1152)^T + b -> out
    gemm_bias_kernel<<<dim3(DIM / 64, ROWS / 128), 256>>>(
        xout_ptr, proj_w, proj_b, out, ROWS, DIM, DIM);
}

// round 6
// speedup vs baseline: 1.4795x; 1.4789x over previous
#include <cuda_runtime.h>
#include <cstdint>
#include <cstddef>

// Problem constants (fixed by setup_inputs)
#define BATCH 4
#define SEQ   1024
#define DIM   1152
#define HEADS 16
#define HDIM  72
#define ROWS  (BATCH*SEQ)          // 4096
#define QKVN  (3*DIM)              // 3456
#define TOTAL_ELEMS 4718592.0f     // B*H*N*hd for loss mean

// Scratch (static device allocation — allowed)
__device__ __align__(16) float g_qkv [(size_t)ROWS * QKVN];   // 56.6 MB
__device__ __align__(16) float g_xout[(size_t)ROWS * DIM];    // 18.9 MB

// ---------------------------------------------------------------------------
// GEMM: C[m,n] = sum_k A[m,k] * W[n,k] + bias[n]
// BM=128, BN=128, BK=16, 256 threads, 8x8 micro-tile, double-buffered smem.
// ---------------------------------------------------------------------------
__global__ __launch_bounds__(256)
void gemm_bias_kernel(const float* __restrict__ A, const float* __restrict__ W,
                      const float* __restrict__ bias, float* __restrict__ C,
                      int M, int N, int K)
{
    __shared__ __align__(16) float As[2][16][128];
    __shared__ __align__(16) float Bs[2][16][128];

    const int tid = threadIdx.x;
    const int tx = tid & 15;          // n micro-tile
    const int ty = tid >> 4;          // m micro-tile
    const int m0 = blockIdx.y * 128;
    const int n0 = blockIdx.x * 128;

    const int lrow = tid >> 2;        // 0..63
    const int lkc  = (tid & 3) << 2;  // 0,4,8,12

    const float* Ap0 = A + (size_t)(m0 + lrow) * K + lkc;
    const float* Ap1 = Ap0 + (size_t)64 * K;
    const float* Wp0 = W + (size_t)(n0 + lrow) * K + lkc;
    const float* Wp1 = Wp0 + (size_t)64 * K;

    float acc[8][8];
#pragma unroll
    for (int i = 0; i < 8; i++)
#pragma unroll
        for (int j = 0; j < 8; j++) acc[i][j] = 0.f;

    float4 pa0, pa1, pb0, pb1;

    // prologue: tile 0
    pa0 = *(const float4*)Ap0;  pa1 = *(const float4*)Ap1;
    pb0 = *(const float4*)Wp0;  pb1 = *(const float4*)Wp1;
    {
        As[0][lkc+0][lrow] = pa0.x; As[0][lkc+1][lrow] = pa0.y;
        As[0][lkc+2][lrow] = pa0.z; As[0][lkc+3][lrow] = pa0.w;
        As[0][lkc+0][lrow+64] = pa1.x; As[0][lkc+1][lrow+64] = pa1.y;
        As[0][lkc+2][lrow+64] = pa1.z; As[0][lkc+3][lrow+64] = pa1.w;
        Bs[0][lkc+0][lrow] = pb0.x; Bs[0][lkc+1][lrow] = pb0.y;
        Bs[0][lkc+2][lrow] = pb0.z; Bs[0][lkc+3][lrow] = pb0.w;
        Bs[0][lkc+0][lrow+64] = pb1.x; Bs[0][lkc+1][lrow+64] = pb1.y;
        Bs[0][lkc+2][lrow+64] = pb1.z; Bs[0][lkc+3][lrow+64] = pb1.w;
    }
    __syncthreads();

    const int nkt = K >> 4;
    for (int kt = 0; kt < nkt; kt++) {
        const int buf = kt & 1;
        if (kt + 1 < nkt) {
            const int off = (kt + 1) << 4;
            pa0 = *(const float4*)(Ap0 + off);
            pa1 = *(const float4*)(Ap1 + off);
            pb0 = *(const float4*)(Wp0 + off);
            pb1 = *(const float4*)(Wp1 + off);
        }
#pragma unroll
        for (int k = 0; k < 16; k++) {
            float4 a0 = *(const float4*)&As[buf][k][ty * 8];
            float4 a1 = *(const float4*)&As[buf][k][ty * 8 + 4];
            float4 b0 = *(const float4*)&Bs[buf][k][tx * 8];
            float4 b1 = *(const float4*)&Bs[buf][k][tx * 8 + 4];
            float am[8] = {a0.x, a0.y, a0.z, a0.w, a1.x, a1.y, a1.z, a1.w};
            float bn[8] = {b0.x, b0.y, b0.z, b0.w, b1.x, b1.y, b1.z, b1.w};
#pragma unroll
            for (int i = 0; i < 8; i++)
#pragma unroll
                for (int j = 0; j < 8; j++) acc[i][j] += am[i] * bn[j];
        }
        if (kt + 1 < nkt) {
            const int nb = buf ^ 1;
            As[nb][lkc+0][lrow] = pa0.x; As[nb][lkc+1][lrow] = pa0.y;
            As[nb][lkc+2][lrow] = pa0.z; As[nb][lkc+3][lrow] = pa0.w;
            As[nb][lkc+0][lrow+64] = pa1.x; As[nb][lkc+1][lrow+64] = pa1.y;
            As[nb][lkc+2][lrow+64] = pa1.z; As[nb][lkc+3][lrow+64] = pa1.w;
            Bs[nb][lkc+0][lrow] = pb0.x; Bs[nb][lkc+1][lrow] = pb0.y;
            Bs[nb][lkc+2][lrow] = pb0.z; Bs[nb][lkc+3][lrow] = pb0.w;
            Bs[nb][lkc+0][lrow+64] = pb1.x; Bs[nb][lkc+1][lrow+64] = pb1.y;
            Bs[nb][lkc+2][lrow+64] = pb1.z; Bs[nb][lkc+3][lrow+64] = pb1.w;
        }
        __syncthreads();
    }

    const float4 bv0 = *(const float4*)&bias[n0 + tx * 8];
    const float4 bv1 = *(const float4*)&bias[n0 + tx * 8 + 4];
#pragma unroll
    for (int i = 0; i < 8; i++) {
        float* cp = C + (size_t)(m0 + ty * 8 + i) * N + n0 + tx * 8;
        float4 o0, o1;
        o0.x = acc[i][0] + bv0.x; o0.y = acc[i][1] + bv0.y;
        o0.z = acc[i][2] + bv0.z; o0.w = acc[i][3] + bv0.w;
        o1.x = acc[i][4] + bv1.x; o1.y = acc[i][5] + bv1.y;
        o1.z = acc[i][6] + bv1.z; o1.w = acc[i][7] + bv1.w;
        *(float4*)cp = o0;
        *(float4*)(cp + 4) = o1;
    }
}

// ---------------------------------------------------------------------------
// Attention: GEMM-style, no shuffles in hot loops.
// smem layout (floats):
//   Qs [72][64] swizzled-transposed        @ 0      (4608)
//   Ks [72][64] swizzled-transposed        @ 4608   (4608)
//   Vs [64][8 seg][12] (9 dims + 3 pad)    @ 9216   (6144)
//   Ps [64][68]                            @ 15360  (4352)
//   smRow[64]                              @ 19712  (64)
// total 19776 floats = 79104 bytes (dynamic)
// ---------------------------------------------------------------------------
#define AT_SMEM_BYTES (19776 * 4)

__device__ __forceinline__ int qk_idx(int d, int k) {
    // rotation swizzle: conflict-light scatter stores, conflict-free float4 reads
    return d * 64 + ((((k >> 2) + 5 * d) & 15) << 2) + (k & 3);
}
__device__ __forceinline__ int v_idx(int k, int d) {
    int s = d / 9;
    return k * 96 + s * 12 + (d - s * 9);
}

__global__ __launch_bounds__(256)
void attn_kernel(const float* __restrict__ enc_k, const float* __restrict__ enc_v,
                 float* __restrict__ loss_out)
{
    extern __shared__ float sm[];
    float* Qs    = sm;
    float* Ks    = sm + 4608;
    float* Vs    = sm + 9216;
    float* Ps    = sm + 15360;
    float* smRow = sm + 19712;

    const int tid = threadIdx.x;
    const int bh = blockIdx.y, b = bh >> 4, h = bh & 15;
    const int n0 = blockIdx.x * 64;
    const float scale = rsqrtf((float)HDIM);

    // role layouts
    const int s_tx = tid & 15, s_ty = tid >> 4;   // score GEMM: 4 queries x 4 keys
    const int r_row = tid >> 2, r_sub = tid & 3;  // softmax: row, 16-col slice
    const int p_q = tid >> 3, p_dg = tid & 7;     // PV: queries p_q & p_q+32, dims p_dg*9..+8

    // ---- load Q tile once (scaled, swizzled transpose) ----
    {
        const float* qbase = g_qkv + ((size_t)(b * SEQ + n0)) * QKVN + h * HDIM;
#pragma unroll
        for (int r = 0; r < 9; r++) {
            int e = tid + r * 256;
            int q = e / 36, dpp = e - q * 36;
            int d = dpp * 2;
            float2 v = *(const float2*)(qbase + (size_t)q * QKVN + d);
            Qs[qk_idx(d,     q)] = v.x * scale;
            Qs[qk_idx(d + 1, q)] = v.y * scale;
        }
    }

    float xo[18];
    float lsum = 0.f;

    for (int pass = 0; pass < 2; pass++) {
        float m_ = -1e30f, l_ = 0.f;   // softmax-role running stats (row r_row)
        float O[18];
#pragma unroll
        for (int j = 0; j < 18; j++) O[j] = 0.f;

#pragma unroll 1
        for (int kt = 0; kt < 16; kt++) {
            __syncthreads();   // Ks/Vs/Ps free from previous tile
            // ---- load K (swizzled transpose) + V (segmented) ----
            if (pass == 0) {
                const float* kb = g_qkv + ((size_t)(b * SEQ + kt * 64)) * QKVN + DIM + h * HDIM;
                const float* vb = kb + DIM;
#pragma unroll
                for (int r = 0; r < 9; r++) {
                    int e = tid + r * 256;
                    int key = e / 36, dpp = e - key * 36;
                    int d = dpp * 2;
                    float2 kv = *(const float2*)(kb + (size_t)key * QKVN + d);
                    float2 vv = *(const float2*)(vb + (size_t)key * QKVN + d);
                    Ks[qk_idx(d,     key)] = kv.x;
                    Ks[qk_idx(d + 1, key)] = kv.y;
                    Vs[v_idx(key, d)]     = vv.x;
                    Vs[v_idx(key, d + 1)] = vv.y;
                }
            } else {
                const float* kb = enc_k + ((size_t)bh * SEQ + kt * 64) * HDIM;
                const float* vb = enc_v + ((size_t)bh * SEQ + kt * 64) * HDIM;
#pragma unroll
                for (int r = 0; r < 9; r++) {
                    int e = tid + r * 256;
                    int key = e / 36, dpp = e - key * 36;
                    int d = dpp * 2;
                    float2 kv = *(const float2*)(kb + (size_t)key * HDIM + d);
                    float2 vv = *(const float2*)(vb + (size_t)key * HDIM + d);
                    Ks[qk_idx(d,     key)] = kv.x;
                    Ks[qk_idx(d + 1, key)] = kv.y;
                    Vs[v_idx(key, d)]     = vv.x;
                    Vs[v_idx(key, d + 1)] = vv.y;
                }
            }
            __syncthreads();

            // ---- scores: S = Q K^T (4x4 per thread) ----
            {
                float s00=0,s01=0,s02=0,s03=0, s10=0,s11=0,s12=0,s13=0;
                float s20=0,s21=0,s22=0,s23=0, s30=0,s31=0,s32=0,s33=0;
#pragma unroll 8
                for (int d = 0; d < 72; d++) {
                    float4 qv = *(const float4*)&Qs[d * 64 + (((s_ty + 5 * d) & 15) << 2)];
                    float4 kv = *(const float4*)&Ks[d * 64 + (((s_tx + 5 * d) & 15) << 2)];
                    s00 += qv.x*kv.x; s01 += qv.x*kv.y; s02 += qv.x*kv.z; s03 += qv.x*kv.w;
                    s10 += qv.y*kv.x; s11 += qv.y*kv.y; s12 += qv.y*kv.z; s13 += qv.y*kv.w;
                    s20 += qv.z*kv.x; s21 += qv.z*kv.y; s22 += qv.z*kv.z; s23 += qv.z*kv.w;
                    s30 += qv.w*kv.x; s31 += qv.w*kv.y; s32 += qv.w*kv.z; s33 += qv.w*kv.w;
                }
                float* pr = Ps + (s_ty * 4) * 68 + s_tx * 4;
                pr[0]=s00; pr[1]=s01; pr[2]=s02; pr[3]=s03;  pr+=68;
                pr[0]=s10; pr[1]=s11; pr[2]=s12; pr[3]=s13;  pr+=68;
                pr[0]=s20; pr[1]=s21; pr[2]=s22; pr[3]=s23;  pr+=68;
                pr[0]=s30; pr[1]=s31; pr[2]=s32; pr[3]=s33;
            }
            __syncthreads();

            // ---- softmax: row r_row, cols r_sub*16..+15 ----
            {
                float* prow = Ps + r_row * 68 + r_sub * 16;
                float4 t0 = *(const float4*)(prow + 0);
                float4 t1 = *(const float4*)(prow + 4);
                float4 t2 = *(const float4*)(prow + 8);
                float4 t3 = *(const float4*)(prow + 12);
                float tmax = fmaxf(fmaxf(fmaxf(t0.x,t0.y),fmaxf(t0.z,t0.w)),
                                   fmaxf(fmaxf(t1.x,t1.y),fmaxf(t1.z,t1.w)));
                tmax = fmaxf(tmax, fmaxf(fmaxf(t2.x,t2.y),fmaxf(t2.z,t2.w)));
                tmax = fmaxf(tmax, fmaxf(fmaxf(t3.x,t3.y),fmaxf(t3.z,t3.w)));
                tmax = fmaxf(tmax, __shfl_xor_sync(0xffffffffu, tmax, 1));
                tmax = fmaxf(tmax, __shfl_xor_sync(0xffffffffu, tmax, 2));
                float nm = fmaxf(m_, tmax);
                float corr = __expf(m_ - nm);
                t0.x=__expf(t0.x-nm); t0.y=__expf(t0.y-nm); t0.z=__expf(t0.z-nm); t0.w=__expf(t0.w-nm);
                t1.x=__expf(t1.x-nm); t1.y=__expf(t1.y-nm); t1.z=__expf(t1.z-nm); t1.w=__expf(t1.w-nm);
                t2.x=__expf(t2.x-nm); t2.y=__expf(t2.y-nm); t2.z=__expf(t2.z-nm); t2.w=__expf(t2.w-nm);
                t3.x=__expf(t3.x-nm); t3.y=__expf(t3.y-nm); t3.z=__expf(t3.z-nm); t3.w=__expf(t3.w-nm);
                float ps = (t0.x+t0.y+t0.z+t0.w) + (t1.x+t1.y+t1.z+t1.w)
                         + (t2.x+t2.y+t2.z+t2.w) + (t3.x+t3.y+t3.z+t3.w);
                ps += __shfl_xor_sync(0xffffffffu, ps, 1);
                ps += __shfl_xor_sync(0xffffffffu, ps, 2);
                l_ = l_ * corr + ps;
                m_ = nm;
                *(float4*)(prow + 0)  = t0;
                *(float4*)(prow + 4)  = t1;
                *(float4*)(prow + 8)  = t2;
                *(float4*)(prow + 12) = t3;
                if (r_sub == 0) smRow[r_row] = corr;
            }
            __syncthreads();

            // ---- PV: O += P @ V (2 queries x 9 dims per thread) ----
            {
                const float c0 = smRow[p_q];
                const float c1 = smRow[p_q + 32];
#pragma unroll
                for (int j = 0; j < 9; j++) { O[j] *= c0; O[9 + j] *= c1; }
                const float* P0 = Ps + p_q * 68;
                const float* P1 = Ps + (p_q + 32) * 68;
                const float* Vb = Vs + p_dg * 12;
#pragma unroll 4
                for (int k = 0; k < 64; k++) {
                    float a0 = P0[k], a1 = P1[k];
                    float4 v0 = *(const float4*)(Vb + k * 96);
                    float4 v1 = *(const float4*)(Vb + k * 96 + 4);
                    float  v2 = Vb[k * 96 + 8];
                    O[0] += a0*v0.x; O[1] += a0*v0.y; O[2] += a0*v0.z; O[3] += a0*v0.w;
                    O[4] += a0*v1.x; O[5] += a0*v1.y; O[6] += a0*v1.z; O[7] += a0*v1.w;
                    O[8] += a0*v2;
                    O[9]  += a1*v0.x; O[10] += a1*v0.y; O[11] += a1*v0.z; O[12] += a1*v0.w;
                    O[13] += a1*v1.x; O[14] += a1*v1.y; O[15] += a1*v1.z; O[16] += a1*v1.w;
                    O[17] += a1*v2;
                }
            }
        }

        // ---- pass epilogue ----
        __syncthreads();                       // all PV reads of smRow done
        if (r_sub == 0) smRow[r_row] = 1.0f / l_;
        __syncthreads();
        const float i0 = smRow[p_q];
        const float i1 = smRow[p_q + 32];
        if (pass == 0) {
            float* d0 = g_xout + ((size_t)(b * SEQ + n0 + p_q)) * DIM + h * HDIM + p_dg * 9;
            float* d1 = g_xout + ((size_t)(b * SEQ + n0 + p_q + 32)) * DIM + h * HDIM + p_dg * 9;
#pragma unroll
            for (int j = 0; j < 9; j++) {
                xo[j]     = O[j] * i0;     d0[j] = xo[j];
                xo[9 + j] = O[9 + j] * i1; d1[j] = xo[9 + j];
            }
        } else {
#pragma unroll
            for (int j = 0; j < 9; j++) {
                float e0 = xo[j]     - O[j] * i0;
                float e1 = xo[9 + j] - O[9 + j] * i1;
                lsum += e0 * e0 + e1 * e1;
            }
        }
    }

    // loss reduction: warp reduce + one atomic per warp
    lsum *= (1.0f / TOTAL_ELEMS);
#pragma unroll
    for (int o = 16; o > 0; o >>= 1)
        lsum += __shfl_down_sync(0xffffffffu, lsum, o);
    if ((tid & 31) == 0) atomicAdd(loss_out, lsum);
}

// ---------------------------------------------------------------------------
extern "C" void kernel_launch(void* const* d_in, const int* in_sizes, int n_in,
                              void* d_out, int out_size)
{
    const float* x      = (const float*)d_in[0];
    const float* enc_k  = (const float*)d_in[1];
    const float* enc_v  = (const float*)d_in[2];
    const float* qkv_w  = (const float*)d_in[3];
    const float* qkv_b  = (const float*)d_in[4];
    const float* proj_w = (const float*)d_in[5];
    const float* proj_b = (const float*)d_in[6];
    float* out = (float*)d_out;
    float* loss_ptr = out + (out_size - 1);

    float* qkv_ptr = nullptr;
    float* xout_ptr = nullptr;
    cudaGetSymbolAddress((void**)&qkv_ptr,  g_qkv);
    cudaGetSymbolAddress((void**)&xout_ptr, g_xout);

    static bool attr_set = false;
    if (!attr_set) {
        cudaFuncSetAttribute(attn_kernel,
                             cudaFuncAttributeMaxDynamicSharedMemorySize,
                             AT_SMEM_BYTES);
        attr_set = true;
    }

    cudaMemsetAsync(loss_ptr, 0, sizeof(float));

    // 1) QKV GEMM: (4096,1152) @ (3456,1152)^T + b -> g_qkv
    gemm_bias_kernel<<<dim3(QKVN / 128, ROWS / 128), 256>>>(
        x, qkv_w, qkv_b, qkv_ptr, ROWS, QKVN, DIM);

    // 2) Dual attention + loss -> g_xout, loss scalar
    attn_kernel<<<dim3(SEQ / 64, BATCH * HEADS), 256, AT_SMEM_BYTES>>>(
        enc_k, enc_v, loss_ptr);

    // 3) Proj GEMM: (4096,1152) @ (1152,1152)^T + b -> out
    gemm_bias_kernel<<<dim3(DIM / 128, ROWS / 128), 256>>>(
        xout_ptr, proj_w, proj_b, out, ROWS, DIM, DIM);
}